// round 4
// baseline (speedup 1.0000x reference)
#include <cuda_runtime.h>
#include <cuda_bf16.h>

#define N_NODES 100000
#define N_EDGES 1600000
#define C_IN  64
#define C_HID 64
#define C_OUT 32

#define SCAN_B 256
#define N_SCAN_BLOCKS ((N_NODES + SCAN_B - 1) / SCAN_B)   // 391

// ---------------- scratch (device globals; no allocation allowed) ----------
__device__ float g_deg[N_NODES];
__device__ float g_dinv[N_NODES];
__device__ int   g_cnt[N_NODES];     // in-degree (edge count)
__device__ int   g_fill[N_NODES];    // scatter cursor (starts at row offset)
__device__ int   g_row[N_NODES];     // exclusive scan of cnt
__device__ int   g_bsum[512];
__device__ int   g_boff[512];
__device__ int2  g_epack[N_EDGES];   // CSR-permuted {src, norm-bits}
__device__ float g_h1[N_NODES * C_HID];
__device__ float g_r [N_NODES * C_HID];
__device__ float g_h2[N_NODES * C_OUT];

// ---------------- 1. init ---------------------------------------------------
__global__ void k_init() {
    int i = blockIdx.x * blockDim.x + threadIdx.x;
    if (i < N_NODES) { g_deg[i] = 1.0f; g_cnt[i] = 0; }
}

// ---------------- 2. degree histograms (4 edges / thread) -------------------
// edge_index is int32 on device: src = ei[e], dst = ei[N_EDGES+e].
__global__ void k_pre(const int* __restrict__ ei,
                      const float* __restrict__ ew) {
    int i = blockIdx.x * blockDim.x + threadIdx.x;     // i < N_EDGES/4
    if (i >= N_EDGES / 4) return;
    int4   d4 = ((const int4*)(ei + N_EDGES))[i];
    float4 w4 = ((const float4*)ew)[i];
    atomicAdd(&g_cnt[d4.x], 1);  atomicAdd(&g_deg[d4.x], w4.x);
    atomicAdd(&g_cnt[d4.y], 1);  atomicAdd(&g_deg[d4.y], w4.y);
    atomicAdd(&g_cnt[d4.z], 1);  atomicAdd(&g_deg[d4.z], w4.z);
    atomicAdd(&g_cnt[d4.w], 1);  atomicAdd(&g_deg[d4.w], w4.w);
}

// ---------------- 3. block scan of cnt (+ fused dinv) ------------------------
__global__ void k_scan1() {
    __shared__ int sm[SCAN_B];
    int gid = blockIdx.x * SCAN_B + threadIdx.x;
    int v = (gid < N_NODES) ? g_cnt[gid] : 0;
    if (gid < N_NODES) g_dinv[gid] = rsqrtf(g_deg[gid]);   // deg >= 1 (self loop)
    sm[threadIdx.x] = v;
    __syncthreads();
#pragma unroll
    for (int off = 1; off < SCAN_B; off <<= 1) {
        int t = (threadIdx.x >= off) ? sm[threadIdx.x - off] : 0;
        __syncthreads();
        sm[threadIdx.x] += t;
        __syncthreads();
    }
    int incl = sm[threadIdx.x];
    if (gid < N_NODES) g_row[gid] = incl - v;
    if (threadIdx.x == SCAN_B - 1) g_bsum[blockIdx.x] = incl;
}

__global__ void k_scan2() {
    __shared__ int sm[512];
    int v = (threadIdx.x < N_SCAN_BLOCKS) ? g_bsum[threadIdx.x] : 0;
    sm[threadIdx.x] = v;
    __syncthreads();
#pragma unroll
    for (int off = 1; off < 512; off <<= 1) {
        int t = (threadIdx.x >= off) ? sm[threadIdx.x - off] : 0;
        __syncthreads();
        sm[threadIdx.x] += t;
        __syncthreads();
    }
    g_boff[threadIdx.x] = sm[threadIdx.x] - v;   // exclusive
}

__global__ void k_scan3() {
    int gid = blockIdx.x * SCAN_B + threadIdx.x;
    if (gid < N_NODES) {
        int v = g_row[gid] + g_boff[blockIdx.x];
        g_row[gid]  = v;
        g_fill[gid] = v;     // scatter cursor starts at row offset
    }
}

// ---------------- 4. scatter edges into CSR buckets (packed) ----------------
__global__ void k_scatter(const int* __restrict__ ei,
                          const float* __restrict__ ew) {
    int e = blockIdx.x * blockDim.x + threadIdx.x;
    if (e >= N_EDGES) return;
    int s = ei[e];
    int d = ei[N_EDGES + e];
    float nm = g_dinv[s] * ew[e] * g_dinv[d];
    int pos = atomicAdd(&g_fill[d], 1);
    g_epack[pos] = make_int2(s, __float_as_int(nm));
}

// ---------------- 5. GEMM1: h1 = x @ W1 -------------------------------------
__global__ void __launch_bounds__(128) k_gemm1(const float* __restrict__ x,
                                               const float* __restrict__ W1) {
    __shared__ float Ws[C_IN * C_HID];
    for (int i = threadIdx.x; i < C_IN * C_HID; i += blockDim.x) Ws[i] = W1[i];
    __syncthreads();
    int n = blockIdx.x * blockDim.x + threadIdx.x;
    if (n >= N_NODES) return;

    float acc[C_HID];
#pragma unroll
    for (int j = 0; j < C_HID; j++) acc[j] = 0.0f;

    const float4* xr = (const float4*)(x + (size_t)n * C_IN);
#pragma unroll 1
    for (int kk = 0; kk < C_IN / 4; kk++) {
        float4 xq = __ldg(xr + kk);
        float xv[4] = {xq.x, xq.y, xq.z, xq.w};
#pragma unroll
        for (int u = 0; u < 4; u++) {
            const float* wrow = Ws + (kk * 4 + u) * C_HID;
#pragma unroll
            for (int j = 0; j < C_HID; j++)
                acc[j] = fmaf(xv[u], wrow[j], acc[j]);
        }
    }
    float4* h1o = (float4*)(g_h1 + (size_t)n * C_HID);
#pragma unroll
    for (int q = 0; q < C_HID / 4; q++)
        h1o[q] = make_float4(acc[4*q], acc[4*q+1], acc[4*q+2], acc[4*q+3]);
}

// ---------------- 6. agg1 (warp/node): r = relu(A_hat @ h1 + b1) ------------
// lane owns channels (2*lane, 2*lane+1); gather = one LDG.64 per lane per edge
__global__ void __launch_bounds__(256) k_agg1(const float* __restrict__ b1) {
    int t = blockIdx.x * 256 + threadIdx.x;
    int n = t >> 5;
    int lane = t & 31;
    if (n >= N_NODES) return;

    int row = g_row[n];
    int cnt = g_cnt[n];
    float ax = 0.0f, ay = 0.0f;

    const float2* h1v = (const float2*)g_h1;
    for (int base = 0; base < cnt; base += 32) {
        int k = base + lane;
        int2 ep = make_int2(0, 0);
        if (k < cnt) ep = g_epack[row + k];
        int m = min(32, cnt - base);
#pragma unroll 4
        for (int j = 0; j < m; j++) {
            int   ss = __shfl_sync(0xffffffffu, ep.x, j);
            float ww = __int_as_float(__shfl_sync(0xffffffffu, ep.y, j));
            float2 v = h1v[ss * 32 + lane];
            ax = fmaf(ww, v.x, ax);
            ay = fmaf(ww, v.y, ay);
        }
    }
    float dv = g_dinv[n];
    float dv2 = dv * dv;
    float2 hn = h1v[n * 32 + lane];
    ax = fmaf(dv2, hn.x, ax);
    ay = fmaf(dv2, hn.y, ay);
    float2 bb = ((const float2*)b1)[lane];
    ax = fmaxf(ax + bb.x, 0.0f);
    ay = fmaxf(ay + bb.y, 0.0f);
    ((float2*)g_r)[n * 32 + lane] = make_float2(ax, ay);
}

// ---------------- 7. GEMM2: h2 = r @ W2 -------------------------------------
__global__ void __launch_bounds__(128) k_gemm2(const float* __restrict__ W2) {
    __shared__ float Ws[C_HID * C_OUT];
    for (int i = threadIdx.x; i < C_HID * C_OUT; i += blockDim.x) Ws[i] = W2[i];
    __syncthreads();
    int n = blockIdx.x * blockDim.x + threadIdx.x;
    if (n >= N_NODES) return;

    float acc[C_OUT];
#pragma unroll
    for (int j = 0; j < C_OUT; j++) acc[j] = 0.0f;

    const float4* ar = (const float4*)(g_r + (size_t)n * C_HID);
#pragma unroll 1
    for (int kk = 0; kk < C_HID / 4; kk++) {
        float4 aq = ar[kk];
        float rv[4] = {aq.x, aq.y, aq.z, aq.w};
#pragma unroll
        for (int u = 0; u < 4; u++) {
            const float* wrow = Ws + (kk * 4 + u) * C_OUT;
#pragma unroll
            for (int j = 0; j < C_OUT; j++)
                acc[j] = fmaf(rv[u], wrow[j], acc[j]);
        }
    }
    float4* h2o = (float4*)(g_h2 + (size_t)n * C_OUT);
#pragma unroll
    for (int q = 0; q < C_OUT / 4; q++)
        h2o[q] = make_float4(acc[4*q], acc[4*q+1], acc[4*q+2], acc[4*q+3]);
}

// ---------------- 8. agg2 (warp/node): out = A_hat @ h2 + b2 ----------------
__global__ void __launch_bounds__(256) k_agg2(const float* __restrict__ b2,
                                              float* __restrict__ out) {
    int t = blockIdx.x * 256 + threadIdx.x;
    int n = t >> 5;
    int lane = t & 31;
    if (n >= N_NODES) return;

    int row = g_row[n];
    int cnt = g_cnt[n];
    float a = 0.0f;

    for (int base = 0; base < cnt; base += 32) {
        int k = base + lane;
        int2 ep = make_int2(0, 0);
        if (k < cnt) ep = g_epack[row + k];
        int m = min(32, cnt - base);
#pragma unroll 4
        for (int j = 0; j < m; j++) {
            int   ss = __shfl_sync(0xffffffffu, ep.x, j);
            float ww = __int_as_float(__shfl_sync(0xffffffffu, ep.y, j));
            a = fmaf(ww, g_h2[ss * 32 + lane], a);
        }
    }
    float dv = g_dinv[n];
    a = fmaf(dv * dv, g_h2[n * 32 + lane], a);
    out[n * 32 + lane] = a + b2[lane];
}

// ---------------- launch ----------------------------------------------------
extern "C" void kernel_launch(void* const* d_in, const int* in_sizes, int n_in,
                              void* d_out, int out_size) {
    const float* x  = (const float*)d_in[0];
    const int*   ei = (const int*)d_in[1];     // int32 (JAX x64 disabled)
    const float* ew = (const float*)d_in[2];
    const float* W1 = (const float*)d_in[3];
    const float* b1 = (const float*)d_in[4];
    const float* W2 = (const float*)d_in[5];
    const float* b2 = (const float*)d_in[6];
    float* out = (float*)d_out;

    const int TB = 256;
    k_init   <<<(N_NODES + TB - 1) / TB, TB>>>();
    k_pre    <<<(N_EDGES / 4 + TB - 1) / TB, TB>>>(ei, ew);
    k_scan1  <<<N_SCAN_BLOCKS, SCAN_B>>>();
    k_scan2  <<<1, 512>>>();
    k_scan3  <<<N_SCAN_BLOCKS, SCAN_B>>>();
    k_scatter<<<(N_EDGES + TB - 1) / TB, TB>>>(ei, ew);
    k_gemm1  <<<(N_NODES + 127) / 128, 128>>>(x, W1);
    k_agg1   <<<(N_NODES * 32 + TB - 1) / TB, TB>>>(b1);
    k_gemm2  <<<(N_NODES + 127) / 128, 128>>>(W2);
    k_agg2   <<<(N_NODES * 32 + TB - 1) / TB, TB>>>(b2, out);
}

// round 5
// speedup vs baseline: 1.4138x; 1.4138x over previous
#include <cuda_runtime.h>
#include <cuda_bf16.h>

#define N_NODES 100000
#define N_EDGES 1600000
#define C_IN  64
#define C_HID 64
#define C_OUT 32

#define SCAN_B 256
#define N_SCAN_BLOCKS ((N_NODES + SCAN_B - 1) / SCAN_B)   // 391

// ---------------- scratch (device globals; no allocation allowed) ----------
__device__ float g_deg[N_NODES];
__device__ float g_dinv[N_NODES];
__device__ int   g_cnt[N_NODES];     // in-degree (edge count)
__device__ int   g_fill[N_NODES];    // scatter cursor (init = row offset)
__device__ int   g_row[N_NODES];     // exclusive scan of cnt
__device__ int   g_bsum[512];
__device__ int   g_boff[512];
__device__ int   g_esrc[N_EDGES];    // CSR-permuted src
__device__ float g_enorm[N_EDGES];   // CSR-permuted norm
__device__ float g_h1[N_NODES * C_HID];
__device__ float g_r [N_NODES * C_HID];
__device__ float g_h2[N_NODES * C_OUT];

// ---------------- 1. init ---------------------------------------------------
__global__ void k_init() {
    int i = blockIdx.x * blockDim.x + threadIdx.x;
    if (i < N_NODES) { g_deg[i] = 1.0f; g_cnt[i] = 0; }
}

// ---------------- 2. degree histograms --------------------------------------
// edge_index is int32 on device: src = ei[e], dst = ei[N_EDGES+e].
__global__ void k_pre(const int* __restrict__ ei,
                      const float* __restrict__ ew) {
    int e = blockIdx.x * blockDim.x + threadIdx.x;
    if (e >= N_EDGES) return;
    int d = ei[N_EDGES + e];
    atomicAdd(&g_cnt[d], 1);
    atomicAdd(&g_deg[d], ew[e]);
}

// ---------------- 3. block scan of cnt (+ fused dinv) ------------------------
__global__ void k_scan1() {
    __shared__ int sm[SCAN_B];
    int gid = blockIdx.x * SCAN_B + threadIdx.x;
    int v = (gid < N_NODES) ? g_cnt[gid] : 0;
    if (gid < N_NODES) g_dinv[gid] = rsqrtf(g_deg[gid]);   // deg >= 1 (self loop)
    sm[threadIdx.x] = v;
    __syncthreads();
#pragma unroll
    for (int off = 1; off < SCAN_B; off <<= 1) {
        int t = (threadIdx.x >= off) ? sm[threadIdx.x - off] : 0;
        __syncthreads();
        sm[threadIdx.x] += t;
        __syncthreads();
    }
    int incl = sm[threadIdx.x];
    if (gid < N_NODES) g_row[gid] = incl - v;
    if (threadIdx.x == SCAN_B - 1) g_bsum[blockIdx.x] = incl;
}

__global__ void k_scan2() {
    __shared__ int sm[512];
    int v = (threadIdx.x < N_SCAN_BLOCKS) ? g_bsum[threadIdx.x] : 0;
    sm[threadIdx.x] = v;
    __syncthreads();
#pragma unroll
    for (int off = 1; off < 512; off <<= 1) {
        int t = (threadIdx.x >= off) ? sm[threadIdx.x - off] : 0;
        __syncthreads();
        sm[threadIdx.x] += t;
        __syncthreads();
    }
    g_boff[threadIdx.x] = sm[threadIdx.x] - v;   // exclusive
}

__global__ void k_scan3() {
    int gid = blockIdx.x * SCAN_B + threadIdx.x;
    if (gid < N_NODES) {
        int v = g_row[gid] + g_boff[blockIdx.x];
        g_row[gid]  = v;
        g_fill[gid] = v;     // scatter cursor starts at row offset
    }
}

// ---------------- 4. scatter edges into CSR buckets -------------------------
__global__ void k_scatter(const int* __restrict__ ei,
                          const float* __restrict__ ew) {
    int e = blockIdx.x * blockDim.x + threadIdx.x;
    if (e >= N_EDGES) return;
    int s = ei[e];
    int d = ei[N_EDGES + e];
    float nm = g_dinv[s] * ew[e] * g_dinv[d];
    int pos = atomicAdd(&g_fill[d], 1);
    g_esrc[pos]  = s;
    g_enorm[pos] = nm;
}

// ---------------- 5. GEMM1: h1 = x @ W1 (float4 smem broadcast) -------------
__global__ void __launch_bounds__(128) k_gemm1(const float* __restrict__ x,
                                               const float* __restrict__ W1) {
    __shared__ float4 Ws[C_IN * C_HID / 4];
    for (int i = threadIdx.x; i < C_IN * C_HID / 4; i += blockDim.x)
        Ws[i] = ((const float4*)W1)[i];
    __syncthreads();
    int n = blockIdx.x * blockDim.x + threadIdx.x;
    if (n >= N_NODES) return;

    float4 acc[C_HID / 4];
#pragma unroll
    for (int j = 0; j < C_HID / 4; j++) acc[j] = make_float4(0.f, 0.f, 0.f, 0.f);

    const float4* xr = (const float4*)(x + (size_t)n * C_IN);
#pragma unroll 1
    for (int kk = 0; kk < C_IN / 4; kk++) {
        float4 xq = __ldg(xr + kk);
        float xv[4] = {xq.x, xq.y, xq.z, xq.w};
#pragma unroll
        for (int u = 0; u < 4; u++) {
            const float4* wr = Ws + (kk * 4 + u) * (C_HID / 4);
#pragma unroll
            for (int j = 0; j < C_HID / 4; j++) {
                float4 w4 = wr[j];
                acc[j].x = fmaf(xv[u], w4.x, acc[j].x);
                acc[j].y = fmaf(xv[u], w4.y, acc[j].y);
                acc[j].z = fmaf(xv[u], w4.z, acc[j].z);
                acc[j].w = fmaf(xv[u], w4.w, acc[j].w);
            }
        }
    }
    float4* h1o = (float4*)(g_h1 + (size_t)n * C_HID);
#pragma unroll
    for (int q = 0; q < C_HID / 4; q++) h1o[q] = acc[q];
}

// ---------------- 6. agg1 (warp/node): r = relu(A_hat @ h1 + b1) ------------
// No shuffles: all lanes broadcast-load the edge list (uniform address, L1-hit)
__global__ void __launch_bounds__(256) k_agg1(const float* __restrict__ b1) {
    int t = blockIdx.x * 256 + threadIdx.x;
    int n = t >> 5;
    int lane = t & 31;
    if (n >= N_NODES) return;

    int row = g_row[n];
    int cnt = g_cnt[n];
    const int*   es = g_esrc + row;
    const float* en = g_enorm + row;

    float a0 = 0.0f, a1 = 0.0f;
    int j = 0;
#pragma unroll 1
    for (; j + 2 <= cnt; j += 2) {
        int   s0 = __ldg(es + j);
        int   s1 = __ldg(es + j + 1);
        float w0 = __ldg(en + j);
        float w1 = __ldg(en + j + 1);
        const float* h0 = g_h1 + ((size_t)s0 << 6);
        const float* h1p = g_h1 + ((size_t)s1 << 6);
        float v00 = h0[lane],  v01 = h0[lane + 32];
        float v10 = h1p[lane], v11 = h1p[lane + 32];
        a0 = fmaf(w0, v00, a0);  a1 = fmaf(w0, v01, a1);
        a0 = fmaf(w1, v10, a0);  a1 = fmaf(w1, v11, a1);
    }
    if (j < cnt) {
        int   s0 = __ldg(es + j);
        float w0 = __ldg(en + j);
        const float* h0 = g_h1 + ((size_t)s0 << 6);
        a0 = fmaf(w0, h0[lane],      a0);
        a1 = fmaf(w0, h0[lane + 32], a1);
    }
    float dv = g_dinv[n];
    float dv2 = dv * dv;
    const float* hn = g_h1 + ((size_t)n << 6);
    a0 = fmaf(dv2, hn[lane],      a0);
    a1 = fmaf(dv2, hn[lane + 32], a1);
    a0 = fmaxf(a0 + b1[lane],      0.0f);
    a1 = fmaxf(a1 + b1[lane + 32], 0.0f);
    float* rp = g_r + ((size_t)n << 6);
    rp[lane]      = a0;
    rp[lane + 32] = a1;
}

// ---------------- 7. GEMM2: h2 = r @ W2 (float4 smem broadcast) -------------
__global__ void __launch_bounds__(128) k_gemm2(const float* __restrict__ W2) {
    __shared__ float4 Ws[C_HID * C_OUT / 4];
    for (int i = threadIdx.x; i < C_HID * C_OUT / 4; i += blockDim.x)
        Ws[i] = ((const float4*)W2)[i];
    __syncthreads();
    int n = blockIdx.x * blockDim.x + threadIdx.x;
    if (n >= N_NODES) return;

    float4 acc[C_OUT / 4];
#pragma unroll
    for (int j = 0; j < C_OUT / 4; j++) acc[j] = make_float4(0.f, 0.f, 0.f, 0.f);

    const float4* ar = (const float4*)(g_r + (size_t)n * C_HID);
#pragma unroll 1
    for (int kk = 0; kk < C_HID / 4; kk++) {
        float4 aq = ar[kk];
        float rv[4] = {aq.x, aq.y, aq.z, aq.w};
#pragma unroll
        for (int u = 0; u < 4; u++) {
            const float4* wr = Ws + (kk * 4 + u) * (C_OUT / 4);
#pragma unroll
            for (int j = 0; j < C_OUT / 4; j++) {
                float4 w4 = wr[j];
                acc[j].x = fmaf(rv[u], w4.x, acc[j].x);
                acc[j].y = fmaf(rv[u], w4.y, acc[j].y);
                acc[j].z = fmaf(rv[u], w4.z, acc[j].z);
                acc[j].w = fmaf(rv[u], w4.w, acc[j].w);
            }
        }
    }
    float4* h2o = (float4*)(g_h2 + (size_t)n * C_OUT);
#pragma unroll
    for (int q = 0; q < C_OUT / 4; q++) h2o[q] = acc[q];
}

// ---------------- 8. agg2 (warp/node): out = A_hat @ h2 + b2 ----------------
__global__ void __launch_bounds__(256) k_agg2(const float* __restrict__ b2,
                                              float* __restrict__ out) {
    int t = blockIdx.x * 256 + threadIdx.x;
    int n = t >> 5;
    int lane = t & 31;
    if (n >= N_NODES) return;

    int row = g_row[n];
    int cnt = g_cnt[n];
    const int*   es = g_esrc + row;
    const float* en = g_enorm + row;

    float a = 0.0f;
    int j = 0;
#pragma unroll 1
    for (; j + 2 <= cnt; j += 2) {
        int   s0 = __ldg(es + j);
        int   s1 = __ldg(es + j + 1);
        float w0 = __ldg(en + j);
        float w1 = __ldg(en + j + 1);
        float v0 = g_h2[((size_t)s0 << 5) + lane];
        float v1 = g_h2[((size_t)s1 << 5) + lane];
        a = fmaf(w0, v0, a);
        a = fmaf(w1, v1, a);
    }
    if (j < cnt) {
        int   s0 = __ldg(es + j);
        float w0 = __ldg(en + j);
        a = fmaf(w0, g_h2[((size_t)s0 << 5) + lane], a);
    }
    float dv = g_dinv[n];
    a = fmaf(dv * dv, g_h2[((size_t)n << 5) + lane], a);
    out[((size_t)n << 5) + lane] = a + b2[lane];
}

// ---------------- launch ----------------------------------------------------
extern "C" void kernel_launch(void* const* d_in, const int* in_sizes, int n_in,
                              void* d_out, int out_size) {
    const float* x  = (const float*)d_in[0];
    const int*   ei = (const int*)d_in[1];     // int32 (JAX x64 disabled)
    const float* ew = (const float*)d_in[2];
    const float* W1 = (const float*)d_in[3];
    const float* b1 = (const float*)d_in[4];
    const float* W2 = (const float*)d_in[5];
    const float* b2 = (const float*)d_in[6];
    float* out = (float*)d_out;

    const int TB = 256;
    k_init   <<<(N_NODES + TB - 1) / TB, TB>>>();
    k_pre    <<<(N_EDGES + TB - 1) / TB, TB>>>(ei, ew);
    k_scan1  <<<N_SCAN_BLOCKS, SCAN_B>>>();
    k_scan2  <<<1, 512>>>();
    k_scan3  <<<N_SCAN_BLOCKS, SCAN_B>>>();
    k_scatter<<<(N_EDGES + TB - 1) / TB, TB>>>(ei, ew);
    k_gemm1  <<<(N_NODES + 127) / 128, 128>>>(x, W1);
    k_agg1   <<<(N_NODES * 32 + TB - 1) / TB, TB>>>(b1);
    k_gemm2  <<<(N_NODES + 127) / 128, 128>>>(W2);
    k_agg2   <<<(N_NODES * 32 + TB - 1) / TB, TB>>>(b2, out);
}

// round 6
// speedup vs baseline: 1.4958x; 1.0580x over previous
#include <cuda_runtime.h>
#include <cuda_fp16.h>

#define N_NODES 100000
#define N_EDGES 1600000
#define C_IN  64
#define C_HID 64
#define C_OUT 32

#define SCAN_B 256
#define N_SCAN_BLOCKS ((N_NODES + SCAN_B - 1) / SCAN_B)   // 391

// ---------------- scratch (device globals; no allocation allowed) ----------
__device__ float  g_deg[N_NODES];
__device__ float  g_dinv[N_NODES];
__device__ int    g_cnt[N_NODES];     // in-degree (edge count)
__device__ int    g_fill[N_NODES];    // scatter cursor (init = row offset)
__device__ int    g_row[N_NODES];     // exclusive scan of cnt
__device__ int    g_bsum[512];
__device__ int    g_boff[512];
__device__ int2   g_epack[N_EDGES];   // CSR-permuted {src, norm-bits}
__device__ __half g_h1h[N_NODES * C_HID];   // h1 in fp16 (gather layout)
__device__ float  g_r [N_NODES * C_HID];    // relu output, fp32
__device__ __half g_h2h[N_NODES * C_OUT];   // h2 in fp16

__device__ __forceinline__ unsigned pack2(float a, float b) {
    __half2 h = __floats2half2_rn(a, b);
    return *reinterpret_cast<unsigned*>(&h);
}

// ---------------- 1. init ---------------------------------------------------
__global__ void k_init() {
    int i = blockIdx.x * blockDim.x + threadIdx.x;
    if (i < N_NODES) { g_deg[i] = 1.0f; g_cnt[i] = 0; }
}

// ---------------- 2. degree histograms --------------------------------------
// edge_index is int32 on device: src = ei[e], dst = ei[N_EDGES+e].
__global__ void k_pre(const int* __restrict__ ei,
                      const float* __restrict__ ew) {
    int e = blockIdx.x * blockDim.x + threadIdx.x;
    if (e >= N_EDGES) return;
    int d = ei[N_EDGES + e];
    atomicAdd(&g_cnt[d], 1);
    atomicAdd(&g_deg[d], ew[e]);
}

// ---------------- 3. block scan of cnt (+ fused dinv) ------------------------
__global__ void k_scan1() {
    __shared__ int sm[SCAN_B];
    int gid = blockIdx.x * SCAN_B + threadIdx.x;
    int v = (gid < N_NODES) ? g_cnt[gid] : 0;
    if (gid < N_NODES) g_dinv[gid] = rsqrtf(g_deg[gid]);   // deg >= 1 (self loop)
    sm[threadIdx.x] = v;
    __syncthreads();
#pragma unroll
    for (int off = 1; off < SCAN_B; off <<= 1) {
        int t = (threadIdx.x >= off) ? sm[threadIdx.x - off] : 0;
        __syncthreads();
        sm[threadIdx.x] += t;
        __syncthreads();
    }
    int incl = sm[threadIdx.x];
    if (gid < N_NODES) g_row[gid] = incl - v;
    if (threadIdx.x == SCAN_B - 1) g_bsum[blockIdx.x] = incl;
}

__global__ void k_scan2() {
    __shared__ int sm[512];
    int v = (threadIdx.x < N_SCAN_BLOCKS) ? g_bsum[threadIdx.x] : 0;
    sm[threadIdx.x] = v;
    __syncthreads();
#pragma unroll
    for (int off = 1; off < 512; off <<= 1) {
        int t = (threadIdx.x >= off) ? sm[threadIdx.x - off] : 0;
        __syncthreads();
        sm[threadIdx.x] += t;
        __syncthreads();
    }
    g_boff[threadIdx.x] = sm[threadIdx.x] - v;   // exclusive
}

__global__ void k_scan3() {
    int gid = blockIdx.x * SCAN_B + threadIdx.x;
    if (gid < N_NODES) {
        int v = g_row[gid] + g_boff[blockIdx.x];
        g_row[gid]  = v;
        g_fill[gid] = v;     // scatter cursor starts at row offset
    }
}

// ---------------- 4. scatter edges into CSR buckets (packed STG.64) ---------
__global__ void k_scatter(const int* __restrict__ ei,
                          const float* __restrict__ ew) {
    int e = blockIdx.x * blockDim.x + threadIdx.x;
    if (e >= N_EDGES) return;
    int s = ei[e];
    int d = ei[N_EDGES + e];
    float nm = g_dinv[s] * ew[e] * g_dinv[d];
    int pos = atomicAdd(&g_fill[d], 1);
    g_epack[pos] = make_int2(s, __float_as_int(nm));
}

// ---------------- 5. GEMM1: h1 = x @ W1 -> fp16 ------------------------------
__global__ void __launch_bounds__(128) k_gemm1(const float* __restrict__ x,
                                               const float* __restrict__ W1) {
    __shared__ float4 Ws[C_IN * C_HID / 4];
    for (int i = threadIdx.x; i < C_IN * C_HID / 4; i += blockDim.x)
        Ws[i] = ((const float4*)W1)[i];
    __syncthreads();
    int n = blockIdx.x * blockDim.x + threadIdx.x;
    if (n >= N_NODES) return;

    float4 acc[C_HID / 4];
#pragma unroll
    for (int j = 0; j < C_HID / 4; j++) acc[j] = make_float4(0.f, 0.f, 0.f, 0.f);

    const float4* xr = (const float4*)(x + (size_t)n * C_IN);
#pragma unroll 1
    for (int kk = 0; kk < C_IN / 4; kk++) {
        float4 xq = __ldg(xr + kk);
        float xv[4] = {xq.x, xq.y, xq.z, xq.w};
#pragma unroll
        for (int u = 0; u < 4; u++) {
            const float4* wr = Ws + (kk * 4 + u) * (C_HID / 4);
#pragma unroll
            for (int j = 0; j < C_HID / 4; j++) {
                float4 w4 = wr[j];
                acc[j].x = fmaf(xv[u], w4.x, acc[j].x);
                acc[j].y = fmaf(xv[u], w4.y, acc[j].y);
                acc[j].z = fmaf(xv[u], w4.z, acc[j].z);
                acc[j].w = fmaf(xv[u], w4.w, acc[j].w);
            }
        }
    }
    uint4* ho = (uint4*)(g_h1h + (size_t)n * C_HID);
#pragma unroll
    for (int qq = 0; qq < 8; qq++) {
        uint4 pk;
        pk.x = pack2(acc[2*qq].x,   acc[2*qq].y);
        pk.y = pack2(acc[2*qq].z,   acc[2*qq].w);
        pk.z = pack2(acc[2*qq+1].x, acc[2*qq+1].y);
        pk.w = pack2(acc[2*qq+1].z, acc[2*qq+1].w);
        ho[qq] = pk;
    }
}

// ---------------- 6. agg1 (warp/node): r = relu(A_hat @ h1 + b1) ------------
// lane owns channels (2*lane, 2*lane+1): one LDG.32 (half2) per edge per lane
__global__ void __launch_bounds__(256) k_agg1(const float* __restrict__ b1) {
    int t = blockIdx.x * 256 + threadIdx.x;
    int n = t >> 5;
    int lane = t & 31;
    if (n >= N_NODES) return;

    int row = g_row[n];
    int cnt = g_cnt[n];
    const int2* ep = g_epack + row;
    const __half2* h1v = (const __half2*)g_h1h;

    float a0 = 0.0f, a1 = 0.0f;
    int j = 0;
#pragma unroll 1
    for (; j + 2 <= cnt; j += 2) {
        int2 e0 = __ldg(ep + j);
        int2 e1 = __ldg(ep + j + 1);
        float w0 = __int_as_float(e0.y);
        float w1 = __int_as_float(e1.y);
        float2 v0 = __half22float2(h1v[e0.x * 32 + lane]);
        float2 v1 = __half22float2(h1v[e1.x * 32 + lane]);
        a0 = fmaf(w0, v0.x, a0);  a1 = fmaf(w0, v0.y, a1);
        a0 = fmaf(w1, v1.x, a0);  a1 = fmaf(w1, v1.y, a1);
    }
    if (j < cnt) {
        int2 e0 = __ldg(ep + j);
        float w0 = __int_as_float(e0.y);
        float2 v0 = __half22float2(h1v[e0.x * 32 + lane]);
        a0 = fmaf(w0, v0.x, a0);
        a1 = fmaf(w0, v0.y, a1);
    }
    float dv = g_dinv[n];
    float dv2 = dv * dv;
    float2 hn = __half22float2(h1v[n * 32 + lane]);
    a0 = fmaf(dv2, hn.x, a0);
    a1 = fmaf(dv2, hn.y, a1);
    float2 bb = ((const float2*)b1)[lane];
    a0 = fmaxf(a0 + bb.x, 0.0f);
    a1 = fmaxf(a1 + bb.y, 0.0f);
    ((float2*)g_r)[n * 32 + lane] = make_float2(a0, a1);
}

// ---------------- 7. GEMM2: h2 = r @ W2 -> fp16 ------------------------------
__global__ void __launch_bounds__(128) k_gemm2(const float* __restrict__ W2) {
    __shared__ float4 Ws[C_HID * C_OUT / 4];
    for (int i = threadIdx.x; i < C_HID * C_OUT / 4; i += blockDim.x)
        Ws[i] = ((const float4*)W2)[i];
    __syncthreads();
    int n = blockIdx.x * blockDim.x + threadIdx.x;
    if (n >= N_NODES) return;

    float4 acc[C_OUT / 4];
#pragma unroll
    for (int j = 0; j < C_OUT / 4; j++) acc[j] = make_float4(0.f, 0.f, 0.f, 0.f);

    const float4* ar = (const float4*)(g_r + (size_t)n * C_HID);
#pragma unroll 1
    for (int kk = 0; kk < C_HID / 4; kk++) {
        float4 aq = ar[kk];
        float rv[4] = {aq.x, aq.y, aq.z, aq.w};
#pragma unroll
        for (int u = 0; u < 4; u++) {
            const float4* wr = Ws + (kk * 4 + u) * (C_OUT / 4);
#pragma unroll
            for (int j = 0; j < C_OUT / 4; j++) {
                float4 w4 = wr[j];
                acc[j].x = fmaf(rv[u], w4.x, acc[j].x);
                acc[j].y = fmaf(rv[u], w4.y, acc[j].y);
                acc[j].z = fmaf(rv[u], w4.z, acc[j].z);
                acc[j].w = fmaf(rv[u], w4.w, acc[j].w);
            }
        }
    }
    uint4* ho = (uint4*)(g_h2h + (size_t)n * C_OUT);
#pragma unroll
    for (int qq = 0; qq < 4; qq++) {
        uint4 pk;
        pk.x = pack2(acc[2*qq].x,   acc[2*qq].y);
        pk.y = pack2(acc[2*qq].z,   acc[2*qq].w);
        pk.z = pack2(acc[2*qq+1].x, acc[2*qq+1].y);
        pk.w = pack2(acc[2*qq+1].z, acc[2*qq+1].w);
        ho[qq] = pk;
    }
}

// ---------------- 8. agg2 (warp/node): out = A_hat @ h2 + b2 ----------------
__global__ void __launch_bounds__(256) k_agg2(const float* __restrict__ b2,
                                              float* __restrict__ out) {
    int t = blockIdx.x * 256 + threadIdx.x;
    int n = t >> 5;
    int lane = t & 31;
    if (n >= N_NODES) return;

    int row = g_row[n];
    int cnt = g_cnt[n];
    const int2* ep = g_epack + row;

    float a = 0.0f;
    int j = 0;
#pragma unroll 1
    for (; j + 2 <= cnt; j += 2) {
        int2 e0 = __ldg(ep + j);
        int2 e1 = __ldg(ep + j + 1);
        float w0 = __int_as_float(e0.y);
        float w1 = __int_as_float(e1.y);
        float v0 = __half2float(g_h2h[e0.x * 32 + lane]);
        float v1 = __half2float(g_h2h[e1.x * 32 + lane]);
        a = fmaf(w0, v0, a);
        a = fmaf(w1, v1, a);
    }
    if (j < cnt) {
        int2 e0 = __ldg(ep + j);
        float w0 = __int_as_float(e0.y);
        a = fmaf(w0, __half2float(g_h2h[e0.x * 32 + lane]), a);
    }
    float dv = g_dinv[n];
    a = fmaf(dv * dv, __half2float(g_h2h[n * 32 + lane]), a);
    out[n * 32 + lane] = a + b2[lane];
}

// ---------------- launch ----------------------------------------------------
extern "C" void kernel_launch(void* const* d_in, const int* in_sizes, int n_in,
                              void* d_out, int out_size) {
    const float* x  = (const float*)d_in[0];
    const int*   ei = (const int*)d_in[1];     // int32 (JAX x64 disabled)
    const float* ew = (const float*)d_in[2];
    const float* W1 = (const float*)d_in[3];
    const float* b1 = (const float*)d_in[4];
    const float* W2 = (const float*)d_in[5];
    const float* b2 = (const float*)d_in[6];
    float* out = (float*)d_out;

    const int TB = 256;
    k_init   <<<(N_NODES + TB - 1) / TB, TB>>>();
    k_pre    <<<(N_EDGES + TB - 1) / TB, TB>>>(ei, ew);
    k_scan1  <<<N_SCAN_BLOCKS, SCAN_B>>>();
    k_scan2  <<<1, 512>>>();
    k_scan3  <<<N_SCAN_BLOCKS, SCAN_B>>>();
    k_scatter<<<(N_EDGES + TB - 1) / TB, TB>>>(ei, ew);
    k_gemm1  <<<(N_NODES + 127) / 128, 128>>>(x, W1);
    k_agg1   <<<(N_NODES * 32 + TB - 1) / TB, TB>>>(b1);
    k_gemm2  <<<(N_NODES + 127) / 128, 128>>>(W2);
    k_agg2   <<<(N_NODES * 32 + TB - 1) / TB, TB>>>(b2, out);
}

// round 7
// speedup vs baseline: 1.6372x; 1.0946x over previous
#include <cuda_runtime.h>
#include <cuda_fp16.h>

#define N_NODES 100000
#define N_EDGES 1600000
#define C_IN  64
#define C_HID 64
#define C_OUT 32

#define SCAN_B 256
#define N_SCAN_BLOCKS ((N_NODES + SCAN_B - 1) / SCAN_B)   // 391

// ---------------- scratch (device globals; no allocation allowed) ----------
__device__ float  g_deg[N_NODES];
__device__ float  g_dinv[N_NODES];
__device__ int    g_cnt[N_NODES];     // in-degree (edge count)
__device__ int    g_fill[N_NODES];    // scatter cursor (init = row offset)
__device__ int    g_row[N_NODES];     // exclusive scan of cnt
__device__ int    g_bsum[512];
__device__ int    g_boff[512];
__device__ int2   g_epack[N_EDGES];   // CSR-permuted {src, norm-bits}
__device__ __half g_h1h[N_NODES * C_HID];   // h1 in fp16 (gather layout)
__device__ float  g_r [N_NODES * C_HID];    // relu output, fp32
__device__ __half g_h2h[N_NODES * C_OUT];   // h2 in fp16

__device__ __forceinline__ unsigned pack2(float a, float b) {
    __half2 h = __floats2half2_rn(a, b);
    return *reinterpret_cast<unsigned*>(&h);
}

// ---------------- 1. init ---------------------------------------------------
__global__ void k_init() {
    int i = blockIdx.x * blockDim.x + threadIdx.x;
    if (i < N_NODES) { g_deg[i] = 1.0f; g_cnt[i] = 0; }
}

// ---------------- 2. degree histograms --------------------------------------
// edge_index is int32 on device: src = ei[e], dst = ei[N_EDGES+e].
__global__ void k_pre(const int* __restrict__ ei,
                      const float* __restrict__ ew) {
    int e = blockIdx.x * blockDim.x + threadIdx.x;
    if (e >= N_EDGES) return;
    int d = ei[N_EDGES + e];
    atomicAdd(&g_cnt[d], 1);
    atomicAdd(&g_deg[d], ew[e]);
}

// ---------------- 3. block scan of cnt (+ fused dinv) ------------------------
__global__ void k_scan1() {
    __shared__ int sm[SCAN_B];
    int gid = blockIdx.x * SCAN_B + threadIdx.x;
    int v = (gid < N_NODES) ? g_cnt[gid] : 0;
    if (gid < N_NODES) g_dinv[gid] = rsqrtf(g_deg[gid]);   // deg >= 1 (self loop)
    sm[threadIdx.x] = v;
    __syncthreads();
#pragma unroll
    for (int off = 1; off < SCAN_B; off <<= 1) {
        int t = (threadIdx.x >= off) ? sm[threadIdx.x - off] : 0;
        __syncthreads();
        sm[threadIdx.x] += t;
        __syncthreads();
    }
    int incl = sm[threadIdx.x];
    if (gid < N_NODES) g_row[gid] = incl - v;
    if (threadIdx.x == SCAN_B - 1) g_bsum[blockIdx.x] = incl;
}

__global__ void k_scan2() {
    __shared__ int sm[512];
    int v = (threadIdx.x < N_SCAN_BLOCKS) ? g_bsum[threadIdx.x] : 0;
    sm[threadIdx.x] = v;
    __syncthreads();
#pragma unroll
    for (int off = 1; off < 512; off <<= 1) {
        int t = (threadIdx.x >= off) ? sm[threadIdx.x - off] : 0;
        __syncthreads();
        sm[threadIdx.x] += t;
        __syncthreads();
    }
    g_boff[threadIdx.x] = sm[threadIdx.x] - v;   // exclusive
}

__global__ void k_scan3() {
    int gid = blockIdx.x * SCAN_B + threadIdx.x;
    if (gid < N_NODES) {
        int v = g_row[gid] + g_boff[blockIdx.x];
        g_row[gid]  = v;
        g_fill[gid] = v;     // scatter cursor starts at row offset
    }
}

// ---------------- 4. scatter edges into CSR buckets (packed STG.64) ---------
__global__ void k_scatter(const int* __restrict__ ei,
                          const float* __restrict__ ew) {
    int e = blockIdx.x * blockDim.x + threadIdx.x;
    if (e >= N_EDGES) return;
    int s = ei[e];
    int d = ei[N_EDGES + e];
    float nm = g_dinv[s] * ew[e] * g_dinv[d];
    int pos = atomicAdd(&g_fill[d], 1);
    g_epack[pos] = make_int2(s, __float_as_int(nm));
}

// ---------------- 5. GEMM1: h1 = x @ W1 -> fp16 ------------------------------
__global__ void __launch_bounds__(128) k_gemm1(const float* __restrict__ x,
                                               const float* __restrict__ W1) {
    __shared__ float4 Ws[C_IN * C_HID / 4];
    for (int i = threadIdx.x; i < C_IN * C_HID / 4; i += blockDim.x)
        Ws[i] = ((const float4*)W1)[i];
    __syncthreads();
    int n = blockIdx.x * blockDim.x + threadIdx.x;
    if (n >= N_NODES) return;

    float4 acc[C_HID / 4];
#pragma unroll
    for (int j = 0; j < C_HID / 4; j++) acc[j] = make_float4(0.f, 0.f, 0.f, 0.f);

    const float4* xr = (const float4*)(x + (size_t)n * C_IN);
#pragma unroll 1
    for (int kk = 0; kk < C_IN / 4; kk++) {
        float4 xq = __ldg(xr + kk);
        float xv[4] = {xq.x, xq.y, xq.z, xq.w};
#pragma unroll
        for (int u = 0; u < 4; u++) {
            const float4* wr = Ws + (kk * 4 + u) * (C_HID / 4);
#pragma unroll
            for (int j = 0; j < C_HID / 4; j++) {
                float4 w4 = wr[j];
                acc[j].x = fmaf(xv[u], w4.x, acc[j].x);
                acc[j].y = fmaf(xv[u], w4.y, acc[j].y);
                acc[j].z = fmaf(xv[u], w4.z, acc[j].z);
                acc[j].w = fmaf(xv[u], w4.w, acc[j].w);
            }
        }
    }
    uint4* ho = (uint4*)(g_h1h + (size_t)n * C_HID);
#pragma unroll
    for (int qq = 0; qq < 8; qq++) {
        uint4 pk;
        pk.x = pack2(acc[2*qq].x,   acc[2*qq].y);
        pk.y = pack2(acc[2*qq].z,   acc[2*qq].w);
        pk.z = pack2(acc[2*qq+1].x, acc[2*qq+1].y);
        pk.w = pack2(acc[2*qq+1].z, acc[2*qq+1].w);
        ho[qq] = pk;
    }
}

// ---------------- 6. agg1 (warp/node): r = relu(A_hat @ h1 + b1) ------------
// lane owns channels (2*lane, 2*lane+1); 4 independent gathers in flight
__global__ void __launch_bounds__(256) k_agg1(const float* __restrict__ b1) {
    int t = blockIdx.x * 256 + threadIdx.x;
    int n = t >> 5;
    int lane = t & 31;
    if (n >= N_NODES) return;

    int row = g_row[n];
    int cnt = g_cnt[n];
    const int2* ep = g_epack + row;
    const __half2* h1v = (const __half2*)g_h1h;

    float a0 = 0.0f, a1 = 0.0f;
    int j = 0;
    // peel one edge if row is odd so ep+j becomes 16B-aligned
    if ((row & 1) && cnt > 0) {
        int2 e0 = __ldg(ep);
        float w0 = __int_as_float(e0.y);
        float2 v0 = __half22float2(h1v[e0.x * 32 + lane]);
        a0 = fmaf(w0, v0.x, a0);
        a1 = fmaf(w0, v0.y, a1);
        j = 1;
    }
#pragma unroll 1
    for (; j + 4 <= cnt; j += 4) {
        const int4* p = (const int4*)(ep + j);
        int4 p0 = __ldg(p);        // edges j, j+1
        int4 p1 = __ldg(p + 1);    // edges j+2, j+3
        float2 v0 = __half22float2(h1v[p0.x * 32 + lane]);
        float2 v1 = __half22float2(h1v[p0.z * 32 + lane]);
        float2 v2 = __half22float2(h1v[p1.x * 32 + lane]);
        float2 v3 = __half22float2(h1v[p1.z * 32 + lane]);
        float w0 = __int_as_float(p0.y), w1 = __int_as_float(p0.w);
        float w2 = __int_as_float(p1.y), w3 = __int_as_float(p1.w);
        a0 = fmaf(w0, v0.x, a0);  a1 = fmaf(w0, v0.y, a1);
        a0 = fmaf(w1, v1.x, a0);  a1 = fmaf(w1, v1.y, a1);
        a0 = fmaf(w2, v2.x, a0);  a1 = fmaf(w2, v2.y, a1);
        a0 = fmaf(w3, v3.x, a0);  a1 = fmaf(w3, v3.y, a1);
    }
#pragma unroll 1
    for (; j < cnt; j++) {
        int2 e0 = __ldg(ep + j);
        float w0 = __int_as_float(e0.y);
        float2 v0 = __half22float2(h1v[e0.x * 32 + lane]);
        a0 = fmaf(w0, v0.x, a0);
        a1 = fmaf(w0, v0.y, a1);
    }
    float dv = g_dinv[n];
    float dv2 = dv * dv;
    float2 hn = __half22float2(h1v[n * 32 + lane]);
    a0 = fmaf(dv2, hn.x, a0);
    a1 = fmaf(dv2, hn.y, a1);
    float2 bb = ((const float2*)b1)[lane];
    a0 = fmaxf(a0 + bb.x, 0.0f);
    a1 = fmaxf(a1 + bb.y, 0.0f);
    ((float2*)g_r)[n * 32 + lane] = make_float2(a0, a1);
}

// ---------------- 7. GEMM2: h2 = r @ W2 -> fp16 ------------------------------
__global__ void __launch_bounds__(128) k_gemm2(const float* __restrict__ W2) {
    __shared__ float4 Ws[C_HID * C_OUT / 4];
    for (int i = threadIdx.x; i < C_HID * C_OUT / 4; i += blockDim.x)
        Ws[i] = ((const float4*)W2)[i];
    __syncthreads();
    int n = blockIdx.x * blockDim.x + threadIdx.x;
    if (n >= N_NODES) return;

    float4 acc[C_OUT / 4];
#pragma unroll
    for (int j = 0; j < C_OUT / 4; j++) acc[j] = make_float4(0.f, 0.f, 0.f, 0.f);

    const float4* ar = (const float4*)(g_r + (size_t)n * C_HID);
#pragma unroll 1
    for (int kk = 0; kk < C_HID / 4; kk++) {
        float4 aq = ar[kk];
        float rv[4] = {aq.x, aq.y, aq.z, aq.w};
#pragma unroll
        for (int u = 0; u < 4; u++) {
            const float4* wr = Ws + (kk * 4 + u) * (C_OUT / 4);
#pragma unroll
            for (int j = 0; j < C_OUT / 4; j++) {
                float4 w4 = wr[j];
                acc[j].x = fmaf(rv[u], w4.x, acc[j].x);
                acc[j].y = fmaf(rv[u], w4.y, acc[j].y);
                acc[j].z = fmaf(rv[u], w4.z, acc[j].z);
                acc[j].w = fmaf(rv[u], w4.w, acc[j].w);
            }
        }
    }
    uint4* ho = (uint4*)(g_h2h + (size_t)n * C_OUT);
#pragma unroll
    for (int qq = 0; qq < 4; qq++) {
        uint4 pk;
        pk.x = pack2(acc[2*qq].x,   acc[2*qq].y);
        pk.y = pack2(acc[2*qq].z,   acc[2*qq].w);
        pk.z = pack2(acc[2*qq+1].x, acc[2*qq+1].y);
        pk.w = pack2(acc[2*qq+1].z, acc[2*qq+1].w);
        ho[qq] = pk;
    }
}

// ---------------- 8. agg2 (warp/node): out = A_hat @ h2 + b2 ----------------
__global__ void __launch_bounds__(256) k_agg2(const float* __restrict__ b2,
                                              float* __restrict__ out) {
    int t = blockIdx.x * 256 + threadIdx.x;
    int n = t >> 5;
    int lane = t & 31;
    if (n >= N_NODES) return;

    int row = g_row[n];
    int cnt = g_cnt[n];
    const int2* ep = g_epack + row;

    float a = 0.0f;
    int j = 0;
    if ((row & 1) && cnt > 0) {
        int2 e0 = __ldg(ep);
        a = fmaf(__int_as_float(e0.y), __half2float(g_h2h[e0.x * 32 + lane]), a);
        j = 1;
    }
#pragma unroll 1
    for (; j + 4 <= cnt; j += 4) {
        const int4* p = (const int4*)(ep + j);
        int4 p0 = __ldg(p);
        int4 p1 = __ldg(p + 1);
        float v0 = __half2float(g_h2h[p0.x * 32 + lane]);
        float v1 = __half2float(g_h2h[p0.z * 32 + lane]);
        float v2 = __half2float(g_h2h[p1.x * 32 + lane]);
        float v3 = __half2float(g_h2h[p1.z * 32 + lane]);
        a = fmaf(__int_as_float(p0.y), v0, a);
        a = fmaf(__int_as_float(p0.w), v1, a);
        a = fmaf(__int_as_float(p1.y), v2, a);
        a = fmaf(__int_as_float(p1.w), v3, a);
    }
#pragma unroll 1
    for (; j < cnt; j++) {
        int2 e0 = __ldg(ep + j);
        a = fmaf(__int_as_float(e0.y), __half2float(g_h2h[e0.x * 32 + lane]), a);
    }
    float dv = g_dinv[n];
    a = fmaf(dv * dv, __half2float(g_h2h[n * 32 + lane]), a);
    out[n * 32 + lane] = a + b2[lane];
}

// ---------------- launch ----------------------------------------------------
// k_gemm1 moved to launch slot 4 so the fixed ncu window (-s 5, observed
// offset 2) captures it instead of k_scan2. gemm1 has no CSR dependencies.
extern "C" void kernel_launch(void* const* d_in, const int* in_sizes, int n_in,
                              void* d_out, int out_size) {
    const float* x  = (const float*)d_in[0];
    const int*   ei = (const int*)d_in[1];     // int32 (JAX x64 disabled)
    const float* ew = (const float*)d_in[2];
    const float* W1 = (const float*)d_in[3];
    const float* b1 = (const float*)d_in[4];
    const float* W2 = (const float*)d_in[5];
    const float* b2 = (const float*)d_in[6];
    float* out = (float*)d_out;

    const int TB = 256;
    k_init   <<<(N_NODES + TB - 1) / TB, TB>>>();
    k_pre    <<<(N_EDGES + TB - 1) / TB, TB>>>(ei, ew);
    k_scan1  <<<N_SCAN_BLOCKS, SCAN_B>>>();
    k_gemm1  <<<(N_NODES + 127) / 128, 128>>>(x, W1);   // slot 4 (profiled)
    k_scan2  <<<1, 512>>>();
    k_scan3  <<<N_SCAN_BLOCKS, SCAN_B>>>();
    k_scatter<<<(N_EDGES + TB - 1) / TB, TB>>>(ei, ew);
    k_agg1   <<<(N_NODES * 32 + TB - 1) / TB, TB>>>(b1);
    k_gemm2  <<<(N_NODES + 127) / 128, 128>>>(W2);
    k_agg2   <<<(N_NODES * 32 + TB - 1) / TB, TB>>>(b2, out);
}

// round 9
// speedup vs baseline: 1.9297x; 1.1786x over previous
#include <cuda_runtime.h>
#include <cuda_fp16.h>
#include <mma.h>

using namespace nvcuda;

#define N_NODES 100000
#define N_EDGES 1600000
#define C_IN  64
#define C_HID 64
#define C_OUT 32

#define SCAN_B 256
#define N_SCAN_BLOCKS ((N_NODES + SCAN_B - 1) / SCAN_B)   // 391

// ---------------- scratch (device globals; no allocation allowed) ----------
__device__ float  g_deg[N_NODES];
__device__ float  g_dinv[N_NODES];
__device__ int    g_cnt[N_NODES];     // in-degree (edge count)
__device__ int    g_fill[N_NODES];    // scatter cursor (init = row offset)
__device__ int    g_row[N_NODES];     // exclusive scan of cnt
__device__ int    g_bsum[512];
__device__ int    g_boff[512];
__device__ int2   g_epack[N_EDGES];   // CSR-permuted {src, norm-bits}
__device__ __half g_h1h[N_NODES * C_HID];   // h1 in fp16 (gather layout)
__device__ __half g_rh [N_NODES * C_HID];   // relu output in fp16
__device__ __half g_h2h[N_NODES * C_OUT];   // h2 in fp16

__device__ __forceinline__ unsigned pack2(float a, float b) {
    __half2 h = __floats2half2_rn(a, b);
    return *reinterpret_cast<unsigned*>(&h);
}

// ---------------- 1. init ---------------------------------------------------
__global__ void k_init() {
    int i = blockIdx.x * blockDim.x + threadIdx.x;
    if (i < N_NODES) { g_deg[i] = 1.0f; g_cnt[i] = 0; }
}

// ---------------- 2. degree histograms --------------------------------------
// edge_index is int32 on device: src = ei[e], dst = ei[N_EDGES+e].
__global__ void k_pre(const int* __restrict__ ei,
                      const float* __restrict__ ew) {
    int e = blockIdx.x * blockDim.x + threadIdx.x;
    if (e >= N_EDGES) return;
    int d = ei[N_EDGES + e];
    atomicAdd(&g_cnt[d], 1);
    atomicAdd(&g_deg[d], ew[e]);
}

// ---------------- 3. block scan of cnt (+ fused dinv) ------------------------
__global__ void k_scan1() {
    __shared__ int sm[SCAN_B];
    int gid = blockIdx.x * SCAN_B + threadIdx.x;
    int v = (gid < N_NODES) ? g_cnt[gid] : 0;
    if (gid < N_NODES) g_dinv[gid] = rsqrtf(g_deg[gid]);   // deg >= 1 (self loop)
    sm[threadIdx.x] = v;
    __syncthreads();
#pragma unroll
    for (int off = 1; off < SCAN_B; off <<= 1) {
        int t = (threadIdx.x >= off) ? sm[threadIdx.x - off] : 0;
        __syncthreads();
        sm[threadIdx.x] += t;
        __syncthreads();
    }
    int incl = sm[threadIdx.x];
    if (gid < N_NODES) g_row[gid] = incl - v;
    if (threadIdx.x == SCAN_B - 1) g_bsum[blockIdx.x] = incl;
}

__global__ void k_scan2() {
    __shared__ int sm[512];
    int v = (threadIdx.x < N_SCAN_BLOCKS) ? g_bsum[threadIdx.x] : 0;
    sm[threadIdx.x] = v;
    __syncthreads();
#pragma unroll
    for (int off = 1; off < 512; off <<= 1) {
        int t = (threadIdx.x >= off) ? sm[threadIdx.x - off] : 0;
        __syncthreads();
        sm[threadIdx.x] += t;
        __syncthreads();
    }
    g_boff[threadIdx.x] = sm[threadIdx.x] - v;   // exclusive
}

__global__ void k_scan3() {
    int gid = blockIdx.x * SCAN_B + threadIdx.x;
    if (gid < N_NODES) {
        int v = g_row[gid] + g_boff[blockIdx.x];
        g_row[gid]  = v;
        g_fill[gid] = v;     // scatter cursor starts at row offset
    }
}

// ---------------- 4. scatter edges into CSR buckets (packed STG.64) ---------
__global__ void k_scatter(const int* __restrict__ ei,
                          const float* __restrict__ ew) {
    int e = blockIdx.x * blockDim.x + threadIdx.x;
    if (e >= N_EDGES) return;
    int s = ei[e];
    int d = ei[N_EDGES + e];
    float nm = g_dinv[s] * ew[e] * g_dinv[d];
    int pos = atomicAdd(&g_fill[d], 1);
    g_epack[pos] = make_int2(s, __float_as_int(nm));
}

// ---------------- 5. GEMM1 (HMMA): h1 = x @ W1 -> fp16 ----------------------
// Block: 64 rows, 128 threads (4 warps). Each warp: 16 rows x 64 cols.
#define XLD 72   // padded leading dim (halves / floats)
__global__ void __launch_bounds__(128) k_gemm1(const float* __restrict__ x,
                                               const float* __restrict__ W1) {
    __shared__ __align__(16) __half Wh[C_IN * XLD];
    __shared__ __align__(16) __half Xh[64 * XLD];
    __shared__ __align__(16) float  Cs[64 * XLD];
    int tid = threadIdx.x;
    int m0 = blockIdx.x * 64;

    // W1 (64x64 fp32) -> fp16 smem, ld = XLD
    for (int i = tid; i < C_IN * C_HID; i += 128) {
        int k = i >> 6, n = i & 63;
        Wh[k * XLD + n] = __float2half(W1[i]);
    }
    // x tile (64 rows x 64 cols fp32) -> fp16 smem
    for (int i = tid; i < 64 * 16; i += 128) {       // 16 float4 per row
        int r = i >> 4, c4 = i & 15;
        int gr = m0 + r;
        float4 v = (gr < N_NODES) ? ((const float4*)x)[gr * 16 + c4]
                                  : make_float4(0.f, 0.f, 0.f, 0.f);
        __half2* dst = (__half2*)(Xh + r * XLD + c4 * 4);
        dst[0] = __floats2half2_rn(v.x, v.y);
        dst[1] = __floats2half2_rn(v.z, v.w);
    }
    __syncthreads();

    int w = tid >> 5;
    wmma::fragment<wmma::accumulator, 16, 16, 16, float> c[4];
#pragma unroll
    for (int nt = 0; nt < 4; nt++) wmma::fill_fragment(c[nt], 0.0f);
#pragma unroll
    for (int kt = 0; kt < 4; kt++) {
        wmma::fragment<wmma::matrix_a, 16, 16, 16, __half, wmma::row_major> a;
        wmma::load_matrix_sync(a, Xh + (w * 16) * XLD + kt * 16, XLD);
#pragma unroll
        for (int nt = 0; nt < 4; nt++) {
            wmma::fragment<wmma::matrix_b, 16, 16, 16, __half, wmma::row_major> b;
            wmma::load_matrix_sync(b, Wh + (kt * 16) * XLD + nt * 16, XLD);
            wmma::mma_sync(c[nt], a, b, c[nt]);
        }
    }
#pragma unroll
    for (int nt = 0; nt < 4; nt++)
        wmma::store_matrix_sync(Cs + (w * 16) * XLD + nt * 16, c[nt], XLD,
                                wmma::mem_row_major);
    __syncthreads();

    // pack fp32 -> fp16 and store coalesced (8 uint4 per row)
    for (int i = tid; i < 64 * 8; i += 128) {
        int r = i >> 3, q = i & 7;
        int gr = m0 + r;
        if (gr < N_NODES) {
            const float* src = Cs + r * XLD + q * 8;
            uint4 pk;
            pk.x = pack2(src[0], src[1]);
            pk.y = pack2(src[2], src[3]);
            pk.z = pack2(src[4], src[5]);
            pk.w = pack2(src[6], src[7]);
            ((uint4*)(g_h1h + (size_t)gr * C_HID))[q] = pk;
        }
    }
}

// ---------------- 6. agg1 (warp/node): r = relu(A_hat @ h1 + b1) -> fp16 ----
__global__ void __launch_bounds__(256) k_agg1(const float* __restrict__ b1) {
    int t = blockIdx.x * 256 + threadIdx.x;
    int n = t >> 5;
    int lane = t & 31;
    if (n >= N_NODES) return;

    int row = g_row[n];
    int cnt = g_cnt[n];
    const int2* ep = g_epack + row;
    const __half2* h1v = (const __half2*)g_h1h;

    float a0 = 0.0f, a1 = 0.0f;
    int j = 0;
    if ((row & 1) && cnt > 0) {      // peel for 16B alignment
        int2 e0 = __ldg(ep);
        float w0 = __int_as_float(e0.y);
        float2 v0 = __half22float2(h1v[e0.x * 32 + lane]);
        a0 = fmaf(w0, v0.x, a0);
        a1 = fmaf(w0, v0.y, a1);
        j = 1;
    }
#pragma unroll 1
    for (; j + 4 <= cnt; j += 4) {
        const int4* p = (const int4*)(ep + j);
        int4 p0 = __ldg(p);
        int4 p1 = __ldg(p + 1);
        float2 v0 = __half22float2(h1v[p0.x * 32 + lane]);
        float2 v1 = __half22float2(h1v[p0.z * 32 + lane]);
        float2 v2 = __half22float2(h1v[p1.x * 32 + lane]);
        float2 v3 = __half22float2(h1v[p1.z * 32 + lane]);
        float w0 = __int_as_float(p0.y), w1 = __int_as_float(p0.w);
        float w2 = __int_as_float(p1.y), w3 = __int_as_float(p1.w);
        a0 = fmaf(w0, v0.x, a0);  a1 = fmaf(w0, v0.y, a1);
        a0 = fmaf(w1, v1.x, a0);  a1 = fmaf(w1, v1.y, a1);
        a0 = fmaf(w2, v2.x, a0);  a1 = fmaf(w2, v2.y, a1);
        a0 = fmaf(w3, v3.x, a0);  a1 = fmaf(w3, v3.y, a1);
    }
#pragma unroll 1
    for (; j < cnt; j++) {
        int2 e0 = __ldg(ep + j);
        float w0 = __int_as_float(e0.y);
        float2 v0 = __half22float2(h1v[e0.x * 32 + lane]);
        a0 = fmaf(w0, v0.x, a0);
        a1 = fmaf(w0, v0.y, a1);
    }
    float dv = g_dinv[n];
    float dv2 = dv * dv;
    float2 hn = __half22float2(h1v[n * 32 + lane]);
    a0 = fmaf(dv2, hn.x, a0);
    a1 = fmaf(dv2, hn.y, a1);
    float2 bb = ((const float2*)b1)[lane];
    a0 = fmaxf(a0 + bb.x, 0.0f);
    a1 = fmaxf(a1 + bb.y, 0.0f);
    ((unsigned*)g_rh)[n * 32 + lane] = pack2(a0, a1);
}

// ---------------- 7. GEMM2 (HMMA): h2 = r @ W2 -> fp16 ----------------------
#define WLD2 40   // 32 + 8 pad
__global__ void __launch_bounds__(128) k_gemm2(const float* __restrict__ W2) {
    __shared__ __align__(16) __half Wh[C_HID * WLD2];
    __shared__ __align__(16) __half Rs[64 * XLD];
    __shared__ __align__(16) float  Cs[64 * WLD2];
    int tid = threadIdx.x;
    int m0 = blockIdx.x * 64;

    // W2 (64x32 fp32) -> fp16 smem
    for (int i = tid; i < C_HID * C_OUT; i += 128) {
        int k = i >> 5, n = i & 31;
        Wh[k * WLD2 + n] = __float2half(W2[i]);
    }
    // r tile (64 rows x 64 halves) -> smem (raw copy, 8 uint4 per row)
    for (int i = tid; i < 64 * 8; i += 128) {
        int r = i >> 3, q = i & 7;
        int gr = m0 + r;
        uint4 v = (gr < N_NODES) ? ((const uint4*)(g_rh + (size_t)gr * C_HID))[q]
                                 : make_uint4(0, 0, 0, 0);
        ((uint4*)(Rs + r * XLD))[q] = v;
    }
    __syncthreads();

    int w = tid >> 5;
    wmma::fragment<wmma::accumulator, 16, 16, 16, float> c[2];
#pragma unroll
    for (int nt = 0; nt < 2; nt++) wmma::fill_fragment(c[nt], 0.0f);
#pragma unroll
    for (int kt = 0; kt < 4; kt++) {
        wmma::fragment<wmma::matrix_a, 16, 16, 16, __half, wmma::row_major> a;
        wmma::load_matrix_sync(a, Rs + (w * 16) * XLD + kt * 16, XLD);
#pragma unroll
        for (int nt = 0; nt < 2; nt++) {
            wmma::fragment<wmma::matrix_b, 16, 16, 16, __half, wmma::row_major> b;
            wmma::load_matrix_sync(b, Wh + (kt * 16) * WLD2 + nt * 16, WLD2);
            wmma::mma_sync(c[nt], a, b, c[nt]);
        }
    }
#pragma unroll
    for (int nt = 0; nt < 2; nt++)
        wmma::store_matrix_sync(Cs + (w * 16) * WLD2 + nt * 16, c[nt], WLD2,
                                wmma::mem_row_major);
    __syncthreads();

    // pack fp32 -> fp16, 4 uint4 per row (32 halves)
    for (int i = tid; i < 64 * 4; i += 128) {
        int r = i >> 2, q = i & 3;
        int gr = m0 + r;
        if (gr < N_NODES) {
            const float* src = Cs + r * WLD2 + q * 8;
            uint4 pk;
            pk.x = pack2(src[0], src[1]);
            pk.y = pack2(src[2], src[3]);
            pk.z = pack2(src[4], src[5]);
            pk.w = pack2(src[6], src[7]);
            ((uint4*)(g_h2h + (size_t)gr * C_OUT))[q] = pk;
        }
    }
}

// ---------------- 8. agg2 (warp/node): out = A_hat @ h2 + b2 ----------------
__global__ void __launch_bounds__(256) k_agg2(const float* __restrict__ b2,
                                              float* __restrict__ out) {
    int t = blockIdx.x * 256 + threadIdx.x;
    int n = t >> 5;
    int lane = t & 31;
    if (n >= N_NODES) return;

    int row = g_row[n];
    int cnt = g_cnt[n];
    const int2* ep = g_epack + row;

    float a = 0.0f;
    int j = 0;
    if ((row & 1) && cnt > 0) {
        int2 e0 = __ldg(ep);
        a = fmaf(__int_as_float(e0.y), __half2float(g_h2h[e0.x * 32 + lane]), a);
        j = 1;
    }
#pragma unroll 1
    for (; j + 4 <= cnt; j += 4) {
        const int4* p = (const int4*)(ep + j);
        int4 p0 = __ldg(p);
        int4 p1 = __ldg(p + 1);
        float v0 = __half2float(g_h2h[p0.x * 32 + lane]);
        float v1 = __half2float(g_h2h[p0.z * 32 + lane]);
        float v2 = __half2float(g_h2h[p1.x * 32 + lane]);
        float v3 = __half2float(g_h2h[p1.z * 32 + lane]);
        a = fmaf(__int_as_float(p0.y), v0, a);
        a = fmaf(__int_as_float(p0.w), v1, a);
        a = fmaf(__int_as_float(p1.y), v2, a);
        a = fmaf(__int_as_float(p1.w), v3, a);
    }
#pragma unroll 1
    for (; j < cnt; j++) {
        int2 e0 = __ldg(ep + j);
        a = fmaf(__int_as_float(e0.y), __half2float(g_h2h[e0.x * 32 + lane]), a);
    }
    float dv = g_dinv[n];
    a = fmaf(dv * dv, __half2float(g_h2h[n * 32 + lane]), a);
    out[n * 32 + lane] = a + b2[lane];
}

// ---------------- launch ----------------------------------------------------
// k_gemm1 stays in launch slot 4 so the fixed ncu window captures the new
// HMMA kernel.
extern "C" void kernel_launch(void* const* d_in, const int* in_sizes, int n_in,
                              void* d_out, int out_size) {
    const float* x  = (const float*)d_in[0];
    const int*   ei = (const int*)d_in[1];     // int32 (JAX x64 disabled)
    const float* ew = (const float*)d_in[2];
    const float* W1 = (const float*)d_in[3];
    const float* b1 = (const float*)d_in[4];
    const float* W2 = (const float*)d_in[5];
    const float* b2 = (const float*)d_in[6];
    float* out = (float*)d_out;

    const int TB = 256;
    const int GEMM_BLOCKS = (N_NODES + 63) / 64;   // 1563
    k_init   <<<(N_NODES + TB - 1) / TB, TB>>>();
    k_pre    <<<(N_EDGES + TB - 1) / TB, TB>>>(ei, ew);
    k_scan1  <<<N_SCAN_BLOCKS, SCAN_B>>>();
    k_gemm1  <<<GEMM_BLOCKS, 128>>>(x, W1);        // slot 4 (profiled)
    k_scan2  <<<1, 512>>>();
    k_scan3  <<<N_SCAN_BLOCKS, SCAN_B>>>();
    k_scatter<<<(N_EDGES + TB - 1) / TB, TB>>>(ei, ew);
    k_agg1   <<<(N_NODES * 32 + TB - 1) / TB, TB>>>(b1);
    k_gemm2  <<<GEMM_BLOCKS, 128>>>(W2);
    k_agg2   <<<(N_NODES * 32 + TB - 1) / TB, TB>>>(b2, out);
}